// round 6
// baseline (speedup 1.0000x reference)
#include <cuda_runtime.h>
#include <cstdint>

#define D_MODEL   4096
#define D_SAE     16384
#define K_SPARSE  64
#define N_TOKENS  8192

// ---------------- scratch (no allocations allowed) ----------------
__device__ float g_WdecT[(size_t)D_SAE * D_MODEL];   // 256 MB: W_dec^T, feature-major
__device__ float g_vals[(size_t)N_TOKENS * K_SPARSE];
__device__ int   g_idxs[(size_t)N_TOKENS * K_SPARSE];

// ---------------- encoder: pre = x @ W_enc^T + b_enc ----------------
// A = x (M x K, row-major), B = W_enc (N x K, row-major)  => NT gemm.
// BM=BN=128, BK=8, 256 threads, 8x8 per thread.
// Two-level fp32 accumulation: chunk accumulators over 256 k-values, flushed
// into totals (16 flushes) -> order-noise ~1e-7 instead of ~1.5e-6 for a
// k-sequential chain. This keeps top-k boundary swaps vs the (blocked-sum
// fp32) reference near zero.
#define BM 128
#define BN 128
#define BK 8
#define GROUP 32   // k0-iterations per flush: 32*8 = 256 k-values per chunk

__global__ __launch_bounds__(256, 1)
void encoder_gemm(const float* __restrict__ A,
                  const float* __restrict__ B,
                  const float* __restrict__ bias,
                  float* __restrict__ C)
{
    __shared__ float As[BK][BM];
    __shared__ float Bs[BK][BN];

    const int bm = blockIdx.y * BM;
    const int bn = blockIdx.x * BN;
    const int tid = threadIdx.x;

    const int tr = tid >> 4;          // 0..15  (m sub-tile)
    const int tc = tid & 15;          // 0..15  (n sub-tile)

    const int lr = tid >> 1;          // 0..127 load row
    const int lc = (tid & 1) * 4;     // 0 or 4 load col

    float accT[8][8];                 // running totals
    float acc[8][8];                  // current 256-k chunk
    #pragma unroll
    for (int i = 0; i < 8; i++)
        #pragma unroll
        for (int j = 0; j < 8; j++) { accT[i][j] = 0.0f; acc[i][j] = 0.0f; }

    const float* Aptr = A + (size_t)(bm + lr) * D_MODEL + lc;
    const float* Bptr = B + (size_t)(bn + lr) * D_MODEL + lc;

    const int nK0 = D_MODEL / BK;     // 512
    for (int k0i = 0; k0i < nK0; k0i++) {
        const int k0 = k0i * BK;
        float4 a4 = *(const float4*)(Aptr + k0);
        float4 b4 = *(const float4*)(Bptr + k0);
        As[lc + 0][lr] = a4.x; As[lc + 1][lr] = a4.y;
        As[lc + 2][lr] = a4.z; As[lc + 3][lr] = a4.w;
        Bs[lc + 0][lr] = b4.x; Bs[lc + 1][lr] = b4.y;
        Bs[lc + 2][lr] = b4.z; Bs[lc + 3][lr] = b4.w;
        __syncthreads();

        #pragma unroll
        for (int kk = 0; kk < BK; kk++) {
            float a[8], b[8];
            const float4* ap = (const float4*)&As[kk][tr * 8];
            const float4* bp = (const float4*)&Bs[kk][tc * 8];
            float4 a0 = ap[0], a1 = ap[1];
            float4 b0 = bp[0], b1 = bp[1];
            a[0]=a0.x; a[1]=a0.y; a[2]=a0.z; a[3]=a0.w;
            a[4]=a1.x; a[5]=a1.y; a[6]=a1.z; a[7]=a1.w;
            b[0]=b0.x; b[1]=b0.y; b[2]=b0.z; b[3]=b0.w;
            b[4]=b1.x; b[5]=b1.y; b[6]=b1.z; b[7]=b1.w;
            #pragma unroll
            for (int i = 0; i < 8; i++)
                #pragma unroll
                for (int j = 0; j < 8; j++)
                    acc[i][j] = fmaf(a[i], b[j], acc[i][j]);
        }
        __syncthreads();

        if ((k0i & (GROUP - 1)) == (GROUP - 1)) {   // flush chunk into totals
            #pragma unroll
            for (int i = 0; i < 8; i++)
                #pragma unroll
                for (int j = 0; j < 8; j++) {
                    accT[i][j] += acc[i][j];
                    acc[i][j] = 0.0f;
                }
        }
    }

    // epilogue: add bias (fp32, outside the sum, as in the reference)
    #pragma unroll
    for (int i = 0; i < 8; i++) {
        const int m = bm + tr * 8 + i;
        float* crow = C + (size_t)m * D_SAE + bn + tc * 8;
        #pragma unroll
        for (int j4 = 0; j4 < 2; j4++) {
            float4 v;
            const int n = bn + tc * 8 + j4 * 4;
            v.x = accT[i][j4*4+0] + bias[n+0];
            v.y = accT[i][j4*4+1] + bias[n+1];
            v.z = accT[i][j4*4+2] + bias[n+2];
            v.w = accT[i][j4*4+3] + bias[n+3];
            *(float4*)(crow + j4 * 4) = v;
        }
    }
}

// ---------------- top-k (radix select, 4 x 8-bit passes) ----------------
__device__ __forceinline__ unsigned fkey(float v) {
    unsigned u = __float_as_uint(v);
    return (u & 0x80000000u) ? ~u : (u | 0x80000000u);   // monotonic: larger float -> larger key
}

__global__ void topk_kernel(const float* __restrict__ pre,
                            float* __restrict__ sparse)
{
    const int token = blockIdx.x;
    const float* row = pre + (size_t)token * D_SAE;
    float* srow = sparse + (size_t)token * D_SAE;
    const int tid = threadIdx.x;   // 256 threads

    __shared__ unsigned int hist[256];
    __shared__ unsigned int s_prefix;
    __shared__ int s_remk;
    __shared__ int s_cnt;
    __shared__ int s_eq;

    unsigned prefix = 0;
    int remk = K_SPARSE;

    for (int shift = 24; shift >= 0; shift -= 8) {
        hist[tid] = 0;
        __syncthreads();
        const unsigned hi_mask = (shift == 24) ? 0u : (0xFFFFFFFFu << (shift + 8));
        for (int i = tid; i < D_SAE; i += 256) {
            unsigned key = fkey(row[i]);
            if ((key & hi_mask) == (prefix & hi_mask))
                atomicAdd(&hist[(key >> shift) & 0xFFu], 1u);
        }
        __syncthreads();
        if (tid == 0) {
            int r = remk;
            int b = 255;
            for (; b > 0; b--) {
                int c = (int)hist[b];
                if (c >= r) break;
                r -= c;
            }
            s_prefix = prefix | ((unsigned)b << shift);
            s_remk = r;
        }
        __syncthreads();
        prefix = s_prefix;
        remk = s_remk;
        __syncthreads();
    }

    const unsigned thresh = prefix;   // key of the k-th largest value
    if (tid == 0) { s_cnt = 0; s_eq = 0; }
    __syncthreads();

    float* vout = g_vals + (size_t)token * K_SPARSE;
    int*   iout = g_idxs + (size_t)token * K_SPARSE;

    for (int i = tid; i < D_SAE; i += 256) {
        float v = row[i];
        unsigned key = fkey(v);
        bool take = false;
        if (key > thresh) {
            take = true;
        } else if (key == thresh) {
            int o = atomicAdd(&s_eq, 1);
            if (o < remk) take = true;     // ties: values identical, position choice immaterial
        }
        float out = 0.0f;
        if (take) {
            out = v;
            int slot = atomicAdd(&s_cnt, 1);
            vout[slot] = v;
            iout[slot] = i;
        }
        srow[i] = out;
    }
}

// ---- transpose W_dec (D_MODEL x D_SAE) -> g_WdecT (D_SAE x D_MODEL) ----
__global__ void transpose_kernel(const float* __restrict__ src)
{
    __shared__ float tile[32][33];
    const int f0 = blockIdx.x * 32;
    const int d0 = blockIdx.y * 32;
    const int tx = threadIdx.x, ty = threadIdx.y;   // (32, 8)
    #pragma unroll
    for (int i = 0; i < 32; i += 8)
        tile[ty + i][tx] = src[(size_t)(d0 + ty + i) * D_SAE + f0 + tx];
    __syncthreads();
    #pragma unroll
    for (int i = 0; i < 32; i += 8)
        g_WdecT[(size_t)(f0 + ty + i) * D_MODEL + d0 + tx] = tile[tx][ty + i];
}

// ---------------- sparse decoder: recon = sparse @ W_dec^T + b_dec ----------------
__global__ __launch_bounds__(256)
void decoder_kernel(const float* __restrict__ b_dec,
                    float* __restrict__ recon)
{
    const int token = blockIdx.x;
    const int tid = threadIdx.x;   // 256 threads, 16 outputs each

    __shared__ float s_v[K_SPARSE];
    __shared__ int   s_f[K_SPARSE];
    if (tid < K_SPARSE) {
        s_v[tid] = g_vals[(size_t)token * K_SPARSE + tid];
        s_f[tid] = g_idxs[(size_t)token * K_SPARSE + tid];
    }
    __syncthreads();

    float acc[16];
    #pragma unroll
    for (int i = 0; i < 16; i++) acc[i] = b_dec[tid + i * 256];

    for (int j = 0; j < K_SPARSE; j++) {
        const float v = s_v[j];
        const float* w = g_WdecT + (size_t)s_f[j] * D_MODEL;
        #pragma unroll
        for (int i = 0; i < 16; i++)
            acc[i] = fmaf(v, w[tid + i * 256], acc[i]);
    }

    float* out = recon + (size_t)token * D_MODEL;
    #pragma unroll
    for (int i = 0; i < 16; i++) out[tid + i * 256] = acc[i];
}

// ---------------- launch ----------------
extern "C" void kernel_launch(void* const* d_in, const int* in_sizes, int n_in,
                              void* d_out, int out_size)
{
    const float* x     = (const float*)d_in[0];   // (N_TOKENS, D_MODEL)
    const float* W_enc = (const float*)d_in[1];   // (D_SAE, D_MODEL)
    const float* b_enc = (const float*)d_in[2];   // (D_SAE,)
    const float* W_dec = (const float*)d_in[3];   // (D_MODEL, D_SAE)
    const float* b_dec = (const float*)d_in[4];   // (D_MODEL,)

    float* out    = (float*)d_out;
    float* recon  = out;                                        // N_TOKENS * D_MODEL
    float* sparse = recon  + (size_t)N_TOKENS * D_MODEL;        // N_TOKENS * D_SAE
    float* pre    = sparse + (size_t)N_TOKENS * D_SAE;          // N_TOKENS * D_SAE

    // 1) encoder GEMM (two-level fp32 accumulation) -> pre_acts
    dim3 gridE(D_SAE / BN, N_TOKENS / BM);
    encoder_gemm<<<gridE, 256>>>(x, W_enc, b_enc, pre);

    // 2) transpose W_dec for the sparse decoder
    transpose_kernel<<<dim3(D_SAE / 32, D_MODEL / 32), dim3(32, 8)>>>(W_dec);

    // 3) per-token top-64 -> sparse_acts (dense) + compact (idx, val) lists
    topk_kernel<<<N_TOKENS, 256>>>(pre, sparse);

    // 4) sparse decoder -> reconstruction
    decoder_kernel<<<N_TOKENS, 256>>>(b_dec, recon);
}

// round 10
// speedup vs baseline: 3.6091x; 3.6091x over previous
#include <cuda_runtime.h>
#include <cstdint>

#define D_MODEL   4096
#define D_SAE     16384
#define K_SPARSE  64
#define N_TOKENS  8192

// ---------------- scratch (no allocations allowed) ----------------
__device__ float g_WdecT[(size_t)D_SAE * D_MODEL];   // 256 MB: W_dec^T, feature-major
__device__ float g_vals[(size_t)N_TOKENS * K_SPARSE];
__device__ int   g_idxs[(size_t)N_TOKENS * K_SPARSE];

__device__ __forceinline__ float tf32r(float x) {
    uint32_t in = __float_as_uint(x), out;
    asm("cvt.rna.tf32.f32 %0, %1;" : "=r"(out) : "r"(in));
    return __uint_as_float(out);
}

// ============ encoder: pre = x @ W_enc^T + b_enc via mma.sync TF32 ============
// A = x (M x K row-major), B = W_enc (N x K row-major) -> NT gemm.
// BM=BN=128, BK=16. 256 threads = 8 warps as 2(m) x 4(n); warp tile 64x32.
// Per k8-step per warp: 4 m-tiles x 4 n-tiles of mma.m16n8k8.tf32.
#define BM 128
#define BN 128
#define BK 16
#define BKP 20          // padded k-stride (words): conflict-free fragment loads
#define GROUP_M 16
#define TILES_M (N_TOKENS / BM)   // 64
#define TILES_N (D_SAE / BN)      // 128

__device__ __forceinline__ void mma_tf32(float c[4], uint32_t a0, uint32_t a1,
                                         uint32_t a2, uint32_t a3,
                                         uint32_t b0, uint32_t b1) {
    asm volatile(
        "mma.sync.aligned.m16n8k8.row.col.f32.tf32.tf32.f32 "
        "{%0,%1,%2,%3}, {%4,%5,%6,%7}, {%8,%9}, {%0,%1,%2,%3};"
        : "+f"(c[0]), "+f"(c[1]), "+f"(c[2]), "+f"(c[3])
        : "r"(a0), "r"(a1), "r"(a2), "r"(a3), "r"(b0), "r"(b1));
}

__global__ __launch_bounds__(256, 2)
void encoder_mma(const float* __restrict__ A,     // x: (8192, 4096)
                 const float* __restrict__ B,     // W_enc: (16384, 4096)
                 const float* __restrict__ bias,
                 float* __restrict__ C)           // pre: (8192, 16384)
{
    __shared__ float As[2][BM][BKP];
    __shared__ float Bs[2][BN][BKP];

    const int tid  = threadIdx.x;
    const int wid  = tid >> 5;
    const int lane = tid & 31;
    const int g    = lane >> 2;      // groupID 0..7
    const int t    = lane & 3;       // thread-in-group 0..3

    // supertiled block mapping (L2 reuse): 16 M-tiles per N-sweep
    const int per_group = GROUP_M * TILES_N;
    const int grp = blockIdx.x / per_group;
    const int rem = blockIdx.x % per_group;
    const int tn  = rem / GROUP_M;
    const int tm  = grp * GROUP_M + (rem % GROUP_M);
    const int bm  = tm * BM;
    const int bn  = tn * BN;

    const int wm = (wid >> 2) * 64;  // warp m-offset: 0 or 64
    const int wn = (wid & 3) * 32;   // warp n-offset: 0,32,64,96

    // global load mapping: thread handles rows (tid>>2) and (tid>>2)+64, float4 col (tid&3)
    const int lrow = tid >> 2;
    const int lc4  = tid & 3;
    const float* Aptr = A + (size_t)(bm + lrow) * D_MODEL + lc4 * 4;
    const float* Bptr = B + (size_t)(bn + lrow) * D_MODEL + lc4 * 4;

    float acc[4][4][4];
    #pragma unroll
    for (int i = 0; i < 4; i++)
        #pragma unroll
        for (int j = 0; j < 4; j++)
            #pragma unroll
            for (int r = 0; r < 4; r++) acc[i][j][r] = 0.0f;

    // preload tile 0
    float4 pa0 = *(const float4*)(Aptr);
    float4 pa1 = *(const float4*)(Aptr + (size_t)64 * D_MODEL);
    float4 pb0 = *(const float4*)(Bptr);
    float4 pb1 = *(const float4*)(Bptr + (size_t)64 * D_MODEL);
    {
        float4 h;
        h.x = tf32r(pa0.x); h.y = tf32r(pa0.y); h.z = tf32r(pa0.z); h.w = tf32r(pa0.w);
        *(float4*)&As[0][lrow][lc4 * 4] = h;
        h.x = tf32r(pa1.x); h.y = tf32r(pa1.y); h.z = tf32r(pa1.z); h.w = tf32r(pa1.w);
        *(float4*)&As[0][lrow + 64][lc4 * 4] = h;
        h.x = tf32r(pb0.x); h.y = tf32r(pb0.y); h.z = tf32r(pb0.z); h.w = tf32r(pb0.w);
        *(float4*)&Bs[0][lrow][lc4 * 4] = h;
        h.x = tf32r(pb1.x); h.y = tf32r(pb1.y); h.z = tf32r(pb1.z); h.w = tf32r(pb1.w);
        *(float4*)&Bs[0][lrow + 64][lc4 * 4] = h;
    }

    const int NIT = D_MODEL / BK;   // 256
    #pragma unroll 1
    for (int it = 0; it < NIT; it++) {
        const int s = it & 1;
        __syncthreads();            // smem[s] ready for all; smem[s^1] free to write

        // prefetch next tile (global -> regs)
        if (it + 1 < NIT) {
            const int k0 = (it + 1) * BK;
            pa0 = *(const float4*)(Aptr + k0);
            pa1 = *(const float4*)(Aptr + (size_t)64 * D_MODEL + k0);
            pb0 = *(const float4*)(Bptr + k0);
            pb1 = *(const float4*)(Bptr + (size_t)64 * D_MODEL + k0);
        }

        // compute: 2 k8-steps on smem[s]
        #pragma unroll
        for (int ks = 0; ks < 2; ks++) {
            const int k = ks * 8;
            uint32_t af[4][4], bf[4][2];
            #pragma unroll
            for (int i = 0; i < 4; i++) {
                const int r0 = wm + i * 16 + g;
                af[i][0] = __float_as_uint(As[s][r0][k + t]);
                af[i][1] = __float_as_uint(As[s][r0 + 8][k + t]);
                af[i][2] = __float_as_uint(As[s][r0][k + t + 4]);
                af[i][3] = __float_as_uint(As[s][r0 + 8][k + t + 4]);
            }
            #pragma unroll
            for (int j = 0; j < 4; j++) {
                const int n0 = wn + j * 8 + g;
                bf[j][0] = __float_as_uint(Bs[s][n0][k + t]);
                bf[j][1] = __float_as_uint(Bs[s][n0][k + t + 4]);
            }
            #pragma unroll
            for (int i = 0; i < 4; i++)
                #pragma unroll
                for (int j = 0; j < 4; j++)
                    mma_tf32(acc[i][j], af[i][0], af[i][1], af[i][2], af[i][3],
                             bf[j][0], bf[j][1]);
        }

        // stage next tile (cvt.rna + STS into smem[s^1])
        if (it + 1 < NIT) {
            const int d = s ^ 1;
            float4 h;
            h.x = tf32r(pa0.x); h.y = tf32r(pa0.y); h.z = tf32r(pa0.z); h.w = tf32r(pa0.w);
            *(float4*)&As[d][lrow][lc4 * 4] = h;
            h.x = tf32r(pa1.x); h.y = tf32r(pa1.y); h.z = tf32r(pa1.z); h.w = tf32r(pa1.w);
            *(float4*)&As[d][lrow + 64][lc4 * 4] = h;
            h.x = tf32r(pb0.x); h.y = tf32r(pb0.y); h.z = tf32r(pb0.z); h.w = tf32r(pb0.w);
            *(float4*)&Bs[d][lrow][lc4 * 4] = h;
            h.x = tf32r(pb1.x); h.y = tf32r(pb1.y); h.z = tf32r(pb1.z); h.w = tf32r(pb1.w);
            *(float4*)&Bs[d][lrow + 64][lc4 * 4] = h;
        }
    }

    // epilogue: c0:(g,2t) c1:(g,2t+1) c2:(g+8,2t) c3:(g+8,2t+1) per 16x8 tile
    #pragma unroll
    for (int i = 0; i < 4; i++) {
        const int r0 = bm + wm + i * 16 + g;
        #pragma unroll
        for (int j = 0; j < 4; j++) {
            const int c0 = bn + wn + j * 8 + 2 * t;
            const float bz0 = bias[c0], bz1 = bias[c0 + 1];
            float* p0 = C + (size_t)r0 * D_SAE + c0;
            float* p1 = C + (size_t)(r0 + 8) * D_SAE + c0;
            float2 v0 = make_float2(acc[i][j][0] + bz0, acc[i][j][1] + bz1);
            float2 v1 = make_float2(acc[i][j][2] + bz0, acc[i][j][3] + bz1);
            *(float2*)p0 = v0;
            *(float2*)p1 = v1;
        }
    }
}

// ================= top-k (radix select + borderline exact recheck) =================
__device__ __forceinline__ unsigned fkey(float v) {
    unsigned u = __float_as_uint(v);
    return (u & 0x80000000u) ? ~u : (u | 0x80000000u);
}
__device__ __forceinline__ float key_to_float(unsigned k) {
    unsigned u = (k & 0x80000000u) ? (k & 0x7FFFFFFFu) : ~k;
    return __uint_as_float(u);
}
#define TK_MARGIN 4e-3f
#define MAX_BL 128

__global__ void topk_kernel(const float* __restrict__ pre,
                            float* __restrict__ sparse,
                            const float* __restrict__ x,
                            const float* __restrict__ W_enc,
                            const float* __restrict__ b_enc)
{
    const int token = blockIdx.x;
    const float* row = pre + (size_t)token * D_SAE;
    float* srow = sparse + (size_t)token * D_SAE;
    const int tid = threadIdx.x;   // 256

    __shared__ unsigned hist[256];
    __shared__ unsigned s_prefix;
    __shared__ int s_remk, s_cnt, s_sure, s_nbl;
    __shared__ int s_bl[MAX_BL];
    __shared__ float s_bl_exact[MAX_BL];
    __shared__ unsigned char s_bl_take[MAX_BL];
    __shared__ float s_red[256];

    unsigned prefix = 0;
    int remk = K_SPARSE;
    for (int shift = 24; shift >= 0; shift -= 8) {
        hist[tid] = 0;
        __syncthreads();
        const unsigned hi_mask = (shift == 24) ? 0u : (0xFFFFFFFFu << (shift + 8));
        for (int i = tid; i < D_SAE; i += 256) {
            unsigned key = fkey(row[i]);
            if ((key & hi_mask) == (prefix & hi_mask))
                atomicAdd(&hist[(key >> shift) & 0xFFu], 1u);
        }
        __syncthreads();
        if (tid == 0) {
            int r = remk, b = 255;
            for (; b > 0; b--) { int c = (int)hist[b]; if (c >= r) break; r -= c; }
            s_prefix = prefix | ((unsigned)b << shift);
            s_remk = r;
        }
        __syncthreads();
        prefix = s_prefix; remk = s_remk;
        __syncthreads();
    }

    const float tval = key_to_float(prefix);     // approx k-th largest value
    const float thi = tval + TK_MARGIN, tlo = tval - TK_MARGIN;

    if (tid == 0) { s_sure = 0; s_nbl = 0; s_cnt = 0; }
    __syncthreads();

    // pass A: count sure-ins, collect borderline
    int local_sure = 0;
    for (int i = tid; i < D_SAE; i += 256) {
        float v = row[i];
        if (v > thi) local_sure++;
        else if (v >= tlo) {
            int p = atomicAdd(&s_nbl, 1);
            if (p < MAX_BL) s_bl[p] = i;
        }
    }
    atomicAdd(&s_sure, local_sure);
    __syncthreads();

    const int nbl = (s_nbl < MAX_BL) ? s_nbl : MAX_BL;
    const int need = K_SPARSE - s_sure;

    if (nbl > need) {
        // exact fp32 recompute of borderline pre-activations (block-cooperative dot)
        const float* xrow = x + (size_t)token * D_MODEL;
        for (int b = 0; b < nbl; b++) {
            const float* wrow = W_enc + (size_t)s_bl[b] * D_MODEL;
            float p = 0.0f;
            for (int j = tid; j < D_MODEL; j += 256)
                p = fmaf(xrow[j], wrow[j], p);
            s_red[tid] = p;
            __syncthreads();
            for (int st = 128; st > 0; st >>= 1) {
                if (tid < st) s_red[tid] += s_red[tid + st];
                __syncthreads();
            }
            if (tid == 0) s_bl_exact[b] = s_red[0] + b_enc[s_bl[b]];
            __syncthreads();
        }
        if (tid == 0) {
            for (int b = 0; b < nbl; b++) {
                int rank = 0;
                for (int b2 = 0; b2 < nbl; b2++) {
                    if (s_bl_exact[b2] > s_bl_exact[b] ||
                        (s_bl_exact[b2] == s_bl_exact[b] && b2 < b)) rank++;
                }
                s_bl_take[b] = (rank < need) ? 1 : 0;
            }
        }
    } else {
        if (tid == 0)
            for (int b = 0; b < nbl; b++) s_bl_take[b] = 1;
    }
    __syncthreads();

    float* vout = g_vals + (size_t)token * K_SPARSE;
    int*   iout = g_idxs + (size_t)token * K_SPARSE;

    for (int i = tid; i < D_SAE; i += 256) {
        float v = row[i];
        bool take = (v > thi);
        if (!take && v >= tlo) {
            for (int b = 0; b < nbl; b++)
                if (s_bl[b] == i) { take = (s_bl_take[b] != 0); break; }
        }
        float outv = 0.0f;
        if (take) {
            outv = v;
            int slot = atomicAdd(&s_cnt, 1);
            if (slot < K_SPARSE) { vout[slot] = v; iout[slot] = i; }
        }
        srow[i] = outv;
    }
}

// ---- transpose W_dec (D_MODEL x D_SAE) -> g_WdecT (D_SAE x D_MODEL) ----
__global__ void transpose_kernel(const float* __restrict__ src)
{
    __shared__ float tile[32][33];
    const int f0 = blockIdx.x * 32;
    const int d0 = blockIdx.y * 32;
    const int tx = threadIdx.x, ty = threadIdx.y;   // (32, 8)
    #pragma unroll
    for (int i = 0; i < 32; i += 8)
        tile[ty + i][tx] = src[(size_t)(d0 + ty + i) * D_SAE + f0 + tx];
    __syncthreads();
    #pragma unroll
    for (int i = 0; i < 32; i += 8)
        g_WdecT[(size_t)(f0 + ty + i) * D_MODEL + d0 + tx] = tile[tx][ty + i];
}

// ---------------- sparse decoder: recon = sparse @ W_dec^T + b_dec ----------------
__global__ __launch_bounds__(256)
void decoder_kernel(const float* __restrict__ b_dec,
                    float* __restrict__ recon)
{
    const int token = blockIdx.x;
    const int tid = threadIdx.x;

    __shared__ float s_v[K_SPARSE];
    __shared__ int   s_f[K_SPARSE];
    if (tid < K_SPARSE) {
        s_v[tid] = g_vals[(size_t)token * K_SPARSE + tid];
        s_f[tid] = g_idxs[(size_t)token * K_SPARSE + tid];
    }
    __syncthreads();

    float acc[16];
    #pragma unroll
    for (int i = 0; i < 16; i++) acc[i] = b_dec[tid + i * 256];

    for (int j = 0; j < K_SPARSE; j++) {
        const float v = s_v[j];
        const float* w = g_WdecT + (size_t)s_f[j] * D_MODEL;
        #pragma unroll
        for (int i = 0; i < 16; i++)
            acc[i] = fmaf(v, w[tid + i * 256], acc[i]);
    }

    float* out = recon + (size_t)token * D_MODEL;
    #pragma unroll
    for (int i = 0; i < 16; i++) out[tid + i * 256] = acc[i];
}

// ---------------- launch ----------------
extern "C" void kernel_launch(void* const* d_in, const int* in_sizes, int n_in,
                              void* d_out, int out_size)
{
    const float* x     = (const float*)d_in[0];
    const float* W_enc = (const float*)d_in[1];
    const float* b_enc = (const float*)d_in[2];
    const float* W_dec = (const float*)d_in[3];
    const float* b_dec = (const float*)d_in[4];

    float* out    = (float*)d_out;
    float* recon  = out;
    float* sparse = recon  + (size_t)N_TOKENS * D_MODEL;
    float* pre    = sparse + (size_t)N_TOKENS * D_SAE;

    // 1) encoder GEMM on tensor cores (mma.sync TF32) -> pre_acts
    encoder_mma<<<TILES_M * TILES_N, 256>>>(x, W_enc, b_enc, pre);

    // 2) transpose W_dec for the sparse decoder
    transpose_kernel<<<dim3(D_SAE / 32, D_MODEL / 32), dim3(32, 8)>>>(W_dec);

    // 3) per-token top-64 with borderline exact recheck
    topk_kernel<<<N_TOKENS, 256>>>(pre, sparse, x, W_enc, b_enc);

    // 4) sparse decoder -> reconstruction
    decoder_kernel<<<N_TOKENS, 256>>>(b_dec, recon);
}

// round 12
// speedup vs baseline: 5.3047x; 1.4698x over previous
#include <cuda_runtime.h>
#include <cuda_fp16.h>
#include <cstdint>

#define D_MODEL   4096
#define D_SAE     16384
#define K_SPARSE  64
#define N_TOKENS  8192

// ---------------- scratch (no allocations allowed) ----------------
__device__ float g_WdecT[(size_t)D_SAE * D_MODEL];   // 256 MB: W_dec^T, feature-major
__device__ float g_vals[(size_t)N_TOKENS * K_SPARSE];
__device__ int   g_idxs[(size_t)N_TOKENS * K_SPARSE];

__device__ __forceinline__ uint32_t f2h2(float lo, float hi) {
    __half2 h = __floats2half2_rn(lo, hi);
    return *(uint32_t*)&h;
}

// ============ encoder: pre = x @ W_enc^T + b_enc via mma.sync FP16 (f32 accum) ============
// A = x (M x K row-major), B = W_enc (N x K row-major) -> NT gemm.
// BM=BN=128, BK=16. 256 threads = 8 warps as 2(m) x 4(n); warp tile 64x32.
// One k16-step per iteration: 16 x mma.m16n8k16.f16 per warp (2048 MACs each).
#define BM 128
#define BN 128
#define BK 16
#define BKP2 12         // padded k-stride in half2 words; (12g+t)%32 all distinct -> conflict-free
#define GROUP_M 16
#define TILES_M (N_TOKENS / BM)   // 64
#define TILES_N (D_SAE / BN)      // 128

__device__ __forceinline__ void mma_f16(float c[4], uint32_t a0, uint32_t a1,
                                        uint32_t a2, uint32_t a3,
                                        uint32_t b0, uint32_t b1) {
    asm volatile(
        "mma.sync.aligned.m16n8k16.row.col.f32.f16.f16.f32 "
        "{%0,%1,%2,%3}, {%4,%5,%6,%7}, {%8,%9}, {%0,%1,%2,%3};"
        : "+f"(c[0]), "+f"(c[1]), "+f"(c[2]), "+f"(c[3])
        : "r"(a0), "r"(a1), "r"(a2), "r"(a3), "r"(b0), "r"(b1));
}

__global__ __launch_bounds__(256, 2)
void encoder_mma(const float* __restrict__ A,     // x: (8192, 4096)
                 const float* __restrict__ B,     // W_enc: (16384, 4096)
                 const float* __restrict__ bias,
                 float* __restrict__ C)           // pre: (8192, 16384)
{
    __shared__ __align__(16) uint32_t As2[2][BM][BKP2];   // half2 tiles
    __shared__ __align__(16) uint32_t Bs2[2][BN][BKP2];

    const int tid  = threadIdx.x;
    const int wid  = tid >> 5;
    const int lane = tid & 31;
    const int g    = lane >> 2;      // groupID 0..7
    const int t    = lane & 3;       // thread-in-group 0..3

    // supertiled block mapping (L2 reuse): 16 M-tiles per N-sweep
    const int per_group = GROUP_M * TILES_N;
    const int grp = blockIdx.x / per_group;
    const int rem = blockIdx.x % per_group;
    const int tn  = rem / GROUP_M;
    const int tm  = grp * GROUP_M + (rem % GROUP_M);
    const int bm  = tm * BM;
    const int bn  = tn * BN;

    const int wm = (wid >> 2) * 64;  // warp m-offset: 0 or 64
    const int wn = (wid & 3) * 32;   // warp n-offset: 0,32,64,96

    // global load mapping: thread handles rows (tid>>2) and (tid>>2)+64, float4 col (tid&3)
    const int lrow = tid >> 2;
    const int lc4  = tid & 3;
    const float* Aptr = A + (size_t)(bm + lrow) * D_MODEL + lc4 * 4;
    const float* Bptr = B + (size_t)(bn + lrow) * D_MODEL + lc4 * 4;

    float acc[4][4][4];
    #pragma unroll
    for (int i = 0; i < 4; i++)
        #pragma unroll
        for (int j = 0; j < 4; j++)
            #pragma unroll
            for (int r = 0; r < 4; r++) acc[i][j][r] = 0.0f;

    // preload tile 0 (convert f32 -> half2 at SMEM store)
    float4 pa0 = *(const float4*)(Aptr);
    float4 pa1 = *(const float4*)(Aptr + (size_t)64 * D_MODEL);
    float4 pb0 = *(const float4*)(Bptr);
    float4 pb1 = *(const float4*)(Bptr + (size_t)64 * D_MODEL);
    {
        *(uint2*)&As2[0][lrow][lc4 * 2]      = make_uint2(f2h2(pa0.x, pa0.y), f2h2(pa0.z, pa0.w));
        *(uint2*)&As2[0][lrow + 64][lc4 * 2] = make_uint2(f2h2(pa1.x, pa1.y), f2h2(pa1.z, pa1.w));
        *(uint2*)&Bs2[0][lrow][lc4 * 2]      = make_uint2(f2h2(pb0.x, pb0.y), f2h2(pb0.z, pb0.w));
        *(uint2*)&Bs2[0][lrow + 64][lc4 * 2] = make_uint2(f2h2(pb1.x, pb1.y), f2h2(pb1.z, pb1.w));
    }

    const int NIT = D_MODEL / BK;   // 256
    #pragma unroll 1
    for (int it = 0; it < NIT; it++) {
        const int s = it & 1;
        __syncthreads();            // smem[s] ready for all; smem[s^1] free to write

        // prefetch next tile (global -> regs)
        if (it + 1 < NIT) {
            const int k0 = (it + 1) * BK;
            pa0 = *(const float4*)(Aptr + k0);
            pa1 = *(const float4*)(Aptr + (size_t)64 * D_MODEL + k0);
            pb0 = *(const float4*)(Bptr + k0);
            pb1 = *(const float4*)(Bptr + (size_t)64 * D_MODEL + k0);
        }

        // compute: one k16-step on smem[s]
        {
            uint32_t af[4][4], bf[4][2];
            #pragma unroll
            for (int i = 0; i < 4; i++) {
                const int r0 = wm + i * 16 + g;
                af[i][0] = As2[s][r0][t];           // (row g,   k 2t..2t+1)
                af[i][1] = As2[s][r0 + 8][t];       // (row g+8, k 2t..2t+1)
                af[i][2] = As2[s][r0][t + 4];       // (row g,   k 2t+8..2t+9)
                af[i][3] = As2[s][r0 + 8][t + 4];
            }
            #pragma unroll
            for (int j = 0; j < 4; j++) {
                const int n0 = wn + j * 8 + g;
                bf[j][0] = Bs2[s][n0][t];
                bf[j][1] = Bs2[s][n0][t + 4];
            }
            #pragma unroll
            for (int i = 0; i < 4; i++)
                #pragma unroll
                for (int j = 0; j < 4; j++)
                    mma_f16(acc[i][j], af[i][0], af[i][1], af[i][2], af[i][3],
                            bf[j][0], bf[j][1]);
        }

        // stage next tile (cvt + STS into smem[s^1])
        if (it + 1 < NIT) {
            const int d = s ^ 1;
            *(uint2*)&As2[d][lrow][lc4 * 2]      = make_uint2(f2h2(pa0.x, pa0.y), f2h2(pa0.z, pa0.w));
            *(uint2*)&As2[d][lrow + 64][lc4 * 2] = make_uint2(f2h2(pa1.x, pa1.y), f2h2(pa1.z, pa1.w));
            *(uint2*)&Bs2[d][lrow][lc4 * 2]      = make_uint2(f2h2(pb0.x, pb0.y), f2h2(pb0.z, pb0.w));
            *(uint2*)&Bs2[d][lrow + 64][lc4 * 2] = make_uint2(f2h2(pb1.x, pb1.y), f2h2(pb1.z, pb1.w));
        }
    }

    // epilogue: c0:(g,2t) c1:(g,2t+1) c2:(g+8,2t) c3:(g+8,2t+1) per 16x8 tile
    #pragma unroll
    for (int i = 0; i < 4; i++) {
        const int r0 = bm + wm + i * 16 + g;
        #pragma unroll
        for (int j = 0; j < 4; j++) {
            const int c0 = bn + wn + j * 8 + 2 * t;
            const float bz0 = bias[c0], bz1 = bias[c0 + 1];
            float* p0 = C + (size_t)r0 * D_SAE + c0;
            float* p1 = C + (size_t)(r0 + 8) * D_SAE + c0;
            float2 v0 = make_float2(acc[i][j][0] + bz0, acc[i][j][1] + bz1);
            float2 v1 = make_float2(acc[i][j][2] + bz0, acc[i][j][3] + bz1);
            *(float2*)p0 = v0;
            *(float2*)p1 = v1;
        }
    }
}

// ================= top-k (radix select + borderline exact recheck) =================
__device__ __forceinline__ unsigned fkey(float v) {
    unsigned u = __float_as_uint(v);
    return (u & 0x80000000u) ? ~u : (u | 0x80000000u);
}
__device__ __forceinline__ float key_to_float(unsigned k) {
    unsigned u = (k & 0x80000000u) ? (k & 0x7FFFFFFFu) : ~k;
    return __uint_as_float(u);
}
#define TK_MARGIN 4e-3f
#define MAX_BL 128

__global__ void topk_kernel(const float* __restrict__ pre,
                            float* __restrict__ sparse,
                            const float* __restrict__ x,
                            const float* __restrict__ W_enc,
                            const float* __restrict__ b_enc)
{
    const int token = blockIdx.x;
    const float* row = pre + (size_t)token * D_SAE;
    float* srow = sparse + (size_t)token * D_SAE;
    const int tid = threadIdx.x;   // 256

    __shared__ unsigned hist[256];
    __shared__ unsigned s_prefix;
    __shared__ int s_remk, s_cnt, s_sure, s_nbl;
    __shared__ int s_bl[MAX_BL];
    __shared__ float s_bl_exact[MAX_BL];
    __shared__ unsigned char s_bl_take[MAX_BL];
    __shared__ float s_red[256];

    unsigned prefix = 0;
    int remk = K_SPARSE;
    for (int shift = 24; shift >= 0; shift -= 8) {
        hist[tid] = 0;
        __syncthreads();
        const unsigned hi_mask = (shift == 24) ? 0u : (0xFFFFFFFFu << (shift + 8));
        for (int i = tid; i < D_SAE; i += 256) {
            unsigned key = fkey(row[i]);
            if ((key & hi_mask) == (prefix & hi_mask))
                atomicAdd(&hist[(key >> shift) & 0xFFu], 1u);
        }
        __syncthreads();
        if (tid == 0) {
            int r = remk, b = 255;
            for (; b > 0; b--) { int c = (int)hist[b]; if (c >= r) break; r -= c; }
            s_prefix = prefix | ((unsigned)b << shift);
            s_remk = r;
        }
        __syncthreads();
        prefix = s_prefix; remk = s_remk;
        __syncthreads();
    }

    const float tval = key_to_float(prefix);     // approx k-th largest value
    const float thi = tval + TK_MARGIN, tlo = tval - TK_MARGIN;

    if (tid == 0) { s_sure = 0; s_nbl = 0; s_cnt = 0; }
    __syncthreads();

    // pass A: count sure-ins, collect borderline
    int local_sure = 0;
    for (int i = tid; i < D_SAE; i += 256) {
        float v = row[i];
        if (v > thi) local_sure++;
        else if (v >= tlo) {
            int p = atomicAdd(&s_nbl, 1);
            if (p < MAX_BL) s_bl[p] = i;
        }
    }
    atomicAdd(&s_sure, local_sure);
    __syncthreads();

    const int nbl = (s_nbl < MAX_BL) ? s_nbl : MAX_BL;
    const int need = K_SPARSE - s_sure;

    if (nbl > need) {
        // exact fp32 recompute of borderline pre-activations (block-cooperative dot)
        const float* xrow = x + (size_t)token * D_MODEL;
        for (int b = 0; b < nbl; b++) {
            const float* wrow = W_enc + (size_t)s_bl[b] * D_MODEL;
            float p = 0.0f;
            for (int j = tid; j < D_MODEL; j += 256)
                p = fmaf(xrow[j], wrow[j], p);
            s_red[tid] = p;
            __syncthreads();
            for (int st = 128; st > 0; st >>= 1) {
                if (tid < st) s_red[tid] += s_red[tid + st];
                __syncthreads();
            }
            if (tid == 0) s_bl_exact[b] = s_red[0] + b_enc[s_bl[b]];
            __syncthreads();
        }
        if (tid == 0) {
            for (int b = 0; b < nbl; b++) {
                int rank = 0;
                for (int b2 = 0; b2 < nbl; b2++) {
                    if (s_bl_exact[b2] > s_bl_exact[b] ||
                        (s_bl_exact[b2] == s_bl_exact[b] && b2 < b)) rank++;
                }
                s_bl_take[b] = (rank < need) ? 1 : 0;
            }
        }
    } else {
        if (tid == 0)
            for (int b = 0; b < nbl; b++) s_bl_take[b] = 1;
    }
    __syncthreads();

    float* vout = g_vals + (size_t)token * K_SPARSE;
    int*   iout = g_idxs + (size_t)token * K_SPARSE;

    for (int i = tid; i < D_SAE; i += 256) {
        float v = row[i];
        bool take = (v > thi);
        if (!take && v >= tlo) {
            for (int b = 0; b < nbl; b++)
                if (s_bl[b] == i) { take = (s_bl_take[b] != 0); break; }
        }
        float outv = 0.0f;
        if (take) {
            outv = v;
            int slot = atomicAdd(&s_cnt, 1);
            if (slot < K_SPARSE) { vout[slot] = v; iout[slot] = i; }
        }
        srow[i] = outv;
    }
}

// ---- transpose W_dec (D_MODEL x D_SAE) -> g_WdecT (D_SAE x D_MODEL) ----
__global__ void transpose_kernel(const float* __restrict__ src)
{
    __shared__ float tile[32][33];
    const int f0 = blockIdx.x * 32;
    const int d0 = blockIdx.y * 32;
    const int tx = threadIdx.x, ty = threadIdx.y;   // (32, 8)
    #pragma unroll
    for (int i = 0; i < 32; i += 8)
        tile[ty + i][tx] = src[(size_t)(d0 + ty + i) * D_SAE + f0 + tx];
    __syncthreads();
    #pragma unroll
    for (int i = 0; i < 32; i += 8)
        g_WdecT[(size_t)(f0 + ty + i) * D_MODEL + d0 + tx] = tile[tx][ty + i];
}

// ---------------- sparse decoder: recon = sparse @ W_dec^T + b_dec ----------------
__global__ __launch_bounds__(256)
void decoder_kernel(const float* __restrict__ b_dec,
                    float* __restrict__ recon)
{
    const int token = blockIdx.x;
    const int tid = threadIdx.x;

    __shared__ float s_v[K_SPARSE];
    __shared__ int   s_f[K_SPARSE];
    if (tid < K_SPARSE) {
        s_v[tid] = g_vals[(size_t)token * K_SPARSE + tid];
        s_f[tid] = g_idxs[(size_t)token * K_SPARSE + tid];
    }
    __syncthreads();

    float acc[16];
    #pragma unroll
    for (int i = 0; i < 16; i++) acc[i] = b_dec[tid + i * 256];

    for (int j = 0; j < K_SPARSE; j++) {
        const float v = s_v[j];
        const float* w = g_WdecT + (size_t)s_f[j] * D_MODEL;
        #pragma unroll
        for (int i = 0; i < 16; i++)
            acc[i] = fmaf(v, w[tid + i * 256], acc[i]);
    }

    float* out = recon + (size_t)token * D_MODEL;
    #pragma unroll
    for (int i = 0; i < 16; i++) out[tid + i * 256] = acc[i];
}

// ---------------- launch ----------------
extern "C" void kernel_launch(void* const* d_in, const int* in_sizes, int n_in,
                              void* d_out, int out_size)
{
    const float* x     = (const float*)d_in[0];
    const float* W_enc = (const float*)d_in[1];
    const float* b_enc = (const float*)d_in[2];
    const float* W_dec = (const float*)d_in[3];
    const float* b_dec = (const float*)d_in[4];

    float* out    = (float*)d_out;
    float* recon  = out;
    float* sparse = recon  + (size_t)N_TOKENS * D_MODEL;
    float* pre    = sparse + (size_t)N_TOKENS * D_SAE;

    // 1) encoder GEMM on tensor cores (mma.sync fp16, f32 accum) -> pre_acts
    encoder_mma<<<TILES_M * TILES_N, 256>>>(x, W_enc, b_enc, pre);

    // 2) transpose W_dec for the sparse decoder
    transpose_kernel<<<dim3(D_SAE / 32, D_MODEL / 32), dim3(32, 8)>>>(W_dec);

    // 3) per-token top-64 with borderline exact recheck
    topk_kernel<<<N_TOKENS, 256>>>(pre, sparse, x, W_enc, b_enc);

    // 4) sparse decoder -> reconstruction
    decoder_kernel<<<N_TOKENS, 256>>>(b_dec, recon);
}

// round 16
// speedup vs baseline: 5.3552x; 1.0095x over previous
#include <cuda_runtime.h>
#include <cuda_fp16.h>
#include <cstdint>

#define D_MODEL   4096
#define D_SAE     16384
#define K_SPARSE  64
#define N_TOKENS  8192

// ---------------- scratch (no allocations allowed) ----------------
__device__ __half g_xh[(size_t)N_TOKENS * D_MODEL];   // 64 MB: x in half
__device__ __half g_wh[(size_t)D_SAE * D_MODEL];      // 128 MB: W_enc in half
__device__ __half g_WdecTh[(size_t)D_SAE * D_MODEL];  // 128 MB: W_dec^T in half
__device__ float  g_vals[(size_t)N_TOKENS * K_SPARSE];
__device__ int    g_idxs[(size_t)N_TOKENS * K_SPARSE];

__device__ __forceinline__ uint32_t f2h2(float lo, float hi) {
    __half2 h = __floats2half2_rn(lo, hi);
    return *(uint32_t*)&h;
}

// ---------------- pre-pass: convert x and W_enc to half (same rounding as before) ----
__global__ void f2h_all(const float* __restrict__ x, const float* __restrict__ we)
{
    const int i = blockIdx.x * blockDim.x + threadIdx.x;
    const int n4x = N_TOKENS * D_MODEL / 4;
    const int n4w = D_SAE * D_MODEL / 4;
    if (i < n4x) {
        float4 v = ((const float4*)x)[i];
        ((uint2*)g_xh)[i] = make_uint2(f2h2(v.x, v.y), f2h2(v.z, v.w));
    }
    if (i < n4w) {
        float4 v = ((const float4*)we)[i];
        ((uint2*)g_wh)[i] = make_uint2(f2h2(v.x, v.y), f2h2(v.z, v.w));
    }
}

// ============ encoder: pre = x @ W_enc^T + b_enc via mma.sync FP16 (f32 accum) ============
#define BM 128
#define BN 128
#define BK 16
#define BKP2 12         // padded k-stride in half2 words; (12g+t)%32 all distinct -> conflict-free
#define GROUP_M 16
#define TILES_M (N_TOKENS / BM)   // 64
#define TILES_N (D_SAE / BN)      // 128

__device__ __forceinline__ void mma_f16(float c[4], uint32_t a0, uint32_t a1,
                                        uint32_t a2, uint32_t a3,
                                        uint32_t b0, uint32_t b1) {
    asm volatile(
        "mma.sync.aligned.m16n8k16.row.col.f32.f16.f16.f32 "
        "{%0,%1,%2,%3}, {%4,%5,%6,%7}, {%8,%9}, {%0,%1,%2,%3};"
        : "+f"(c[0]), "+f"(c[1]), "+f"(c[2]), "+f"(c[3])
        : "r"(a0), "r"(a1), "r"(a2), "r"(a3), "r"(b0), "r"(b1));
}

__global__ __launch_bounds__(256, 2)
void encoder_mma(const float* __restrict__ bias,
                 float* __restrict__ C)           // pre: (8192, 16384)
{
    __shared__ __align__(16) uint32_t As2[2][BM][BKP2];   // half2 tiles
    __shared__ __align__(16) uint32_t Bs2[2][BN][BKP2];

    const int tid  = threadIdx.x;
    const int wid  = tid >> 5;
    const int lane = tid & 31;
    const int g    = lane >> 2;      // groupID 0..7
    const int t    = lane & 3;       // thread-in-group 0..3

    // supertiled block mapping (L2 reuse): 16 M-tiles per N-sweep
    const int per_group = GROUP_M * TILES_N;
    const int grp = blockIdx.x / per_group;
    const int rem = blockIdx.x % per_group;
    const int tn  = rem / GROUP_M;
    const int tm  = grp * GROUP_M + (rem % GROUP_M);
    const int bm  = tm * BM;
    const int bn  = tn * BN;

    const int wm = (wid >> 2) * 64;  // warp m-offset: 0 or 64
    const int wn = (wid & 3) * 32;   // warp n-offset: 0,32,64,96

    // half-load mapping: thread covers one 16B chunk (8 halves) of one row per tile
    const int lrow = tid >> 1;       // 0..127
    const int lc   = (tid & 1);      // which 8-half group
    const __half* Ah = g_xh + (size_t)(bm + lrow) * D_MODEL + lc * 8;
    const __half* Bh = g_wh + (size_t)(bn + lrow) * D_MODEL + lc * 8;

    float acc[4][4][4];
    #pragma unroll
    for (int i = 0; i < 4; i++)
        #pragma unroll
        for (int j = 0; j < 4; j++)
            #pragma unroll
            for (int r = 0; r < 4; r++) acc[i][j][r] = 0.0f;

    // preload tile 0
    uint4 qa = *(const uint4*)(Ah);
    uint4 qb = *(const uint4*)(Bh);
    *(uint4*)&As2[0][lrow][lc * 4] = qa;
    *(uint4*)&Bs2[0][lrow][lc * 4] = qb;

    const int NIT = D_MODEL / BK;   // 256
    #pragma unroll 1
    for (int it = 0; it < NIT; it++) {
        const int s = it & 1;
        __syncthreads();            // smem[s] ready; smem[s^1] free to write

        // prefetch next tile (global half -> regs)
        if (it + 1 < NIT) {
            qa = *(const uint4*)(Ah + (it + 1) * BK);
            qb = *(const uint4*)(Bh + (it + 1) * BK);
        }

        // compute: one k16-step on smem[s]
        {
            uint32_t af[4][4], bf[4][2];
            #pragma unroll
            for (int i = 0; i < 4; i++) {
                const int r0 = wm + i * 16 + g;
                af[i][0] = As2[s][r0][t];
                af[i][1] = As2[s][r0 + 8][t];
                af[i][2] = As2[s][r0][t + 4];
                af[i][3] = As2[s][r0 + 8][t + 4];
            }
            #pragma unroll
            for (int j = 0; j < 4; j++) {
                const int n0 = wn + j * 8 + g;
                bf[j][0] = Bs2[s][n0][t];
                bf[j][1] = Bs2[s][n0][t + 4];
            }
            #pragma unroll
            for (int i = 0; i < 4; i++)
                #pragma unroll
                for (int j = 0; j < 4; j++)
                    mma_f16(acc[i][j], af[i][0], af[i][1], af[i][2], af[i][3],
                            bf[j][0], bf[j][1]);
        }

        // stage next tile
        if (it + 1 < NIT) {
            const int d = s ^ 1;
            *(uint4*)&As2[d][lrow][lc * 4] = qa;
            *(uint4*)&Bs2[d][lrow][lc * 4] = qb;
        }
    }

    // epilogue
    #pragma unroll
    for (int i = 0; i < 4; i++) {
        const int r0 = bm + wm + i * 16 + g;
        #pragma unroll
        for (int j = 0; j < 4; j++) {
            const int c0 = bn + wn + j * 8 + 2 * t;
            const float bz0 = bias[c0], bz1 = bias[c0 + 1];
            float* p0 = C + (size_t)r0 * D_SAE + c0;
            float* p1 = C + (size_t)(r0 + 8) * D_SAE + c0;
            *(float2*)p0 = make_float2(acc[i][j][0] + bz0, acc[i][j][1] + bz1);
            *(float2*)p1 = make_float2(acc[i][j][2] + bz0, acc[i][j][3] + bz1);
        }
    }
}

// ================= top-k (radix select over SMEM-cached row + borderline recheck) =====
__device__ __forceinline__ unsigned fkey(float v) {
    unsigned u = __float_as_uint(v);
    return (u & 0x80000000u) ? ~u : (u | 0x80000000u);
}
__device__ __forceinline__ float key_to_float(unsigned k) {
    unsigned u = (k & 0x80000000u) ? (k & 0x7FFFFFFFu) : ~k;
    return __uint_as_float(u);
}
#define TK_MARGIN 4e-3f
#define MAX_BL 128

__global__ void topk_kernel(const float* __restrict__ pre,
                            float* __restrict__ sparse,
                            const float* __restrict__ x,
                            const float* __restrict__ W_enc,
                            const float* __restrict__ b_enc)
{
    extern __shared__ float srow_s[];          // 16384 floats = 64 KB row cache
    const int token = blockIdx.x;
    const float* row = pre + (size_t)token * D_SAE;
    float* srow = sparse + (size_t)token * D_SAE;
    const int tid = threadIdx.x;   // 256

    __shared__ unsigned hist[256];
    __shared__ unsigned s_prefix;
    __shared__ int s_remk, s_cnt, s_sure, s_nbl;
    __shared__ int s_bl[MAX_BL];
    __shared__ float s_bl_exact[MAX_BL];
    __shared__ unsigned char s_bl_take[MAX_BL];
    __shared__ float s_red[256];

    // cache the row in SMEM (single gmem read)
    #pragma unroll
    for (int t4 = 0; t4 < 16; t4++) {
        const int i4 = tid + t4 * 256;
        ((float4*)srow_s)[i4] = ((const float4*)row)[i4];
    }
    __syncthreads();

    unsigned prefix = 0;
    int remk = K_SPARSE;
    for (int shift = 24; shift >= 0; shift -= 8) {
        hist[tid] = 0;
        __syncthreads();
        const unsigned hi_mask = (shift == 24) ? 0u : (0xFFFFFFFFu << (shift + 8));
        for (int i = tid; i < D_SAE; i += 256) {
            unsigned key = fkey(srow_s[i]);
            if ((key & hi_mask) == (prefix & hi_mask))
                atomicAdd(&hist[(key >> shift) & 0xFFu], 1u);
        }
        __syncthreads();
        if (tid == 0) {
            int r = remk, b = 255;
            for (; b > 0; b--) { int c = (int)hist[b]; if (c >= r) break; r -= c; }
            s_prefix = prefix | ((unsigned)b << shift);
            s_remk = r;
        }
        __syncthreads();
        prefix = s_prefix; remk = s_remk;
        __syncthreads();
    }

    const float tval = key_to_float(prefix);     // approx k-th largest value
    const float thi = tval + TK_MARGIN, tlo = tval - TK_MARGIN;

    if (tid == 0) { s_sure = 0; s_nbl = 0; s_cnt = 0; }
    __syncthreads();

    // pass A: count sure-ins, collect borderline
    int local_sure = 0;
    for (int i = tid; i < D_SAE; i += 256) {
        float v = srow_s[i];
        if (v > thi) local_sure++;
        else if (v >= tlo) {
            int p = atomicAdd(&s_nbl, 1);
            if (p < MAX_BL) s_bl[p] = i;
        }
    }
    atomicAdd(&s_sure, local_sure);
    __syncthreads();

    const int nbl = (s_nbl < MAX_BL) ? s_nbl : MAX_BL;
    const int need = K_SPARSE - s_sure;

    if (nbl > need) {
        // exact fp32 recompute of borderline pre-activations (block-cooperative dot)
        const float* xrow = x + (size_t)token * D_MODEL;
        for (int b = 0; b < nbl; b++) {
            const float* wrow = W_enc + (size_t)s_bl[b] * D_MODEL;
            float p = 0.0f;
            for (int j = tid; j < D_MODEL; j += 256)
                p = fmaf(xrow[j], wrow[j], p);
            s_red[tid] = p;
            __syncthreads();
            for (int st = 128; st > 0; st >>= 1) {
                if (tid < st) s_red[tid] += s_red[tid + st];
                __syncthreads();
            }
            if (tid == 0) s_bl_exact[b] = s_red[0] + b_enc[s_bl[b]];
            __syncthreads();
        }
        if (tid == 0) {
            for (int b = 0; b < nbl; b++) {
                int rank = 0;
                for (int b2 = 0; b2 < nbl; b2++) {
                    if (s_bl_exact[b2] > s_bl_exact[b] ||
                        (s_bl_exact[b2] == s_bl_exact[b] && b2 < b)) rank++;
                }
                s_bl_take[b] = (rank < need) ? 1 : 0;
            }
        }
    } else {
        if (tid == 0)
            for (int b = 0; b < nbl; b++) s_bl_take[b] = 1;
    }
    __syncthreads();

    float* vout = g_vals + (size_t)token * K_SPARSE;
    int*   iout = g_idxs + (size_t)token * K_SPARSE;

    for (int i = tid; i < D_SAE; i += 256) {
        float v = srow_s[i];
        bool take = (v > thi);
        if (!take && v >= tlo) {
            for (int b = 0; b < nbl; b++)
                if (s_bl[b] == i) { take = (s_bl_take[b] != 0); break; }
        }
        float outv = 0.0f;
        if (take) {
            outv = v;
            int slot = atomicAdd(&s_cnt, 1);
            if (slot < K_SPARSE) { vout[slot] = v; iout[slot] = i; }
        }
        srow[i] = outv;
    }
}

// ---- transpose W_dec (D_MODEL x D_SAE) -> g_WdecTh (D_SAE x D_MODEL), half ----
__global__ void transpose_kernel(const float* __restrict__ src)
{
    __shared__ float tile[32][33];
    const int f0 = blockIdx.x * 32;
    const int d0 = blockIdx.y * 32;
    const int tx = threadIdx.x, ty = threadIdx.y;   // (32, 8)
    #pragma unroll
    for (int i = 0; i < 32; i += 8)
        tile[ty + i][tx] = src[(size_t)(d0 + ty + i) * D_SAE + f0 + tx];
    __syncthreads();
    #pragma unroll
    for (int i = 0; i < 32; i += 8)
        g_WdecTh[(size_t)(f0 + ty + i) * D_MODEL + d0 + tx] =
            __float2half_rn(tile[tx][ty + i]);
}

// ---------------- sparse decoder: recon = sparse @ W_dec^T + b_dec (half weights) ------
__global__ __launch_bounds__(256)
void decoder_kernel(const float* __restrict__ b_dec,
                    float* __restrict__ recon)
{
    const int token = blockIdx.x;
    const int tid = threadIdx.x;

    __shared__ float s_v[K_SPARSE];
    __shared__ int   s_f[K_SPARSE];
    if (tid < K_SPARSE) {
        s_v[tid] = g_vals[(size_t)token * K_SPARSE + tid];
        s_f[tid] = g_idxs[(size_t)token * K_SPARSE + tid];
    }
    __syncthreads();

    float2 acc[8];                      // 16 outputs as 8 float2 (coalesced)
    #pragma unroll
    for (int i = 0; i < 8; i++)
        acc[i] = *(const float2*)(b_dec + 2 * (tid + i * 256));

    for (int j = 0; j < K_SPARSE; j++) {
        const float v = s_v[j];
        const __half2* w = (const __half2*)(g_WdecTh + (size_t)s_f[j] * D_MODEL);
        #pragma unroll
        for (int i = 0; i < 8; i++) {
            float2 f = __half22float2(w[tid + i * 256]);
            acc[i].x = fmaf(v, f.x, acc[i].x);
            acc[i].y = fmaf(v, f.y, acc[i].y);
        }
    }

    float* out = recon + (size_t)token * D_MODEL;
    #pragma unroll
    for (int i = 0; i < 8; i++)
        *(float2*)(out + 2 * (tid + i * 256)) = acc[i];
}

// ---------------- launch ----------------
extern "C" void kernel_launch(void* const* d_in, const int* in_sizes, int n_in,
                              void* d_out, int out_size)
{
    const float* x     = (const float*)d_in[0];
    const float* W_enc = (const float*)d_in[1];
    const float* b_enc = (const float*)d_in[2];
    const float* W_dec = (const float*)d_in[3];
    const float* b_dec = (const float*)d_in[4];

    float* out    = (float*)d_out;
    float* recon  = out;
    float* sparse = recon  + (size_t)N_TOKENS * D_MODEL;
    float* pre    = sparse + (size_t)N_TOKENS * D_SAE;

    // opt-in dynamic smem for the 64 KB row cache (function-sticky; harmless on re-call)
    cudaFuncSetAttribute(topk_kernel, cudaFuncAttributeMaxDynamicSharedMemorySize, 65536);

    // 0) convert x, W_enc to half (identical rounding to the in-loop cvt it replaces)
    f2h_all<<<(D_SAE * (D_MODEL / 4) + 255) / 256, 256>>>(x, W_enc);

    // 1) encoder GEMM on tensor cores (mma.sync fp16, f32 accum) -> pre_acts
    encoder_mma<<<TILES_M * TILES_N, 256>>>(b_enc, pre);

    // 2) transpose + half-convert W_dec for the sparse decoder
    transpose_kernel<<<dim3(D_SAE / 32, D_MODEL / 32), dim3(32, 8)>>>(W_dec);

    // 3) per-token top-64 with SMEM row cache + borderline exact recheck
    topk_kernel<<<N_TOKENS, 256, 65536>>>(pre, sparse, x, W_enc, b_enc);

    // 4) sparse decoder (half weights, fp32 accumulate) -> reconstruction
    decoder_kernel<<<N_TOKENS, 256>>>(b_dec, recon);
}

// round 17
// speedup vs baseline: 7.5195x; 1.4042x over previous
#include <cuda_runtime.h>
#include <cuda_fp16.h>
#include <cstdint>

#define D_MODEL   4096
#define D_SAE     16384
#define K_SPARSE  64
#define N_TOKENS  8192

// ---------------- scratch (no allocations allowed) ----------------
__device__ __half g_xh[(size_t)N_TOKENS * D_MODEL];   // 64 MB: x in half
__device__ __half g_wh[(size_t)D_SAE * D_MODEL];      // 128 MB: W_enc in half
__device__ __half g_WdecTh[(size_t)D_SAE * D_MODEL];  // 128 MB: W_dec^T in half
__device__ float  g_vals[(size_t)N_TOKENS * K_SPARSE];
__device__ int    g_idxs[(size_t)N_TOKENS * K_SPARSE];

__device__ __forceinline__ uint32_t f2h2(float lo, float hi) {
    __half2 h = __floats2half2_rn(lo, hi);
    return *(uint32_t*)&h;
}
__device__ __forceinline__ uint32_t smem_u32(const void* p) {
    return (uint32_t)__cvta_generic_to_shared(p);
}

// ---------------- pre-pass: convert x and W_enc to half ----------------
__global__ void f2h_all(const float* __restrict__ x, const float* __restrict__ we)
{
    const int i = blockIdx.x * blockDim.x + threadIdx.x;
    const int n4x = N_TOKENS * D_MODEL / 4;
    const int n4w = D_SAE * D_MODEL / 4;
    if (i < n4x) {
        float4 v = ((const float4*)x)[i];
        ((uint2*)g_xh)[i] = make_uint2(f2h2(v.x, v.y), f2h2(v.z, v.w));
    }
    if (i < n4w) {
        float4 v = ((const float4*)we)[i];
        ((uint2*)g_wh)[i] = make_uint2(f2h2(v.x, v.y), f2h2(v.z, v.w));
    }
}

// ============ encoder: pre = x @ W_enc^T + b_enc via mma.sync FP16 (f32 accum) ============
// cp.async 3-stage pipeline + ldmatrix fragment loads.
#define BM 128
#define BN 128
#define BK 16
#define BKP2 12         // padded k-stride in half2 words; 12r%32 distinct over 8 rows
#define NSTAGE 3
#define GROUP_M 16
#define TILES_M (N_TOKENS / BM)   // 64
#define TILES_N (D_SAE / BN)      // 128
#define STAGE_A_BYTES (BM * BKP2 * 4)   // 6144
#define STAGE_B_BYTES (BN * BKP2 * 4)   // 6144

__device__ __forceinline__ void mma_f16(float c[4], uint32_t a0, uint32_t a1,
                                        uint32_t a2, uint32_t a3,
                                        uint32_t b0, uint32_t b1) {
    asm volatile(
        "mma.sync.aligned.m16n8k16.row.col.f32.f16.f16.f32 "
        "{%0,%1,%2,%3}, {%4,%5,%6,%7}, {%8,%9}, {%0,%1,%2,%3};"
        : "+f"(c[0]), "+f"(c[1]), "+f"(c[2]), "+f"(c[3])
        : "r"(a0), "r"(a1), "r"(a2), "r"(a3), "r"(b0), "r"(b1));
}
__device__ __forceinline__ void ldsm_x4(uint32_t& r0, uint32_t& r1, uint32_t& r2,
                                        uint32_t& r3, uint32_t addr) {
    asm volatile("ldmatrix.sync.aligned.m8n8.x4.shared.b16 {%0,%1,%2,%3}, [%4];"
                 : "=r"(r0), "=r"(r1), "=r"(r2), "=r"(r3) : "r"(addr));
}

__global__ __launch_bounds__(256, 2)
void encoder_mma(const float* __restrict__ bias,
                 float* __restrict__ C)           // pre: (8192, 16384)
{
    __shared__ __align__(16) uint32_t As2[NSTAGE][BM][BKP2];
    __shared__ __align__(16) uint32_t Bs2[NSTAGE][BN][BKP2];

    const int tid  = threadIdx.x;
    const int wid  = tid >> 5;
    const int lane = tid & 31;
    const int g    = lane >> 2;
    const int t    = lane & 3;

    // supertiled block mapping (L2 reuse)
    const int per_group = GROUP_M * TILES_N;
    const int grp = blockIdx.x / per_group;
    const int rem = blockIdx.x % per_group;
    const int tn  = rem / GROUP_M;
    const int tm  = grp * GROUP_M + (rem % GROUP_M);
    const int bm  = tm * BM;
    const int bn  = tn * BN;

    const int wm = (wid >> 2) * 64;
    const int wn = (wid & 3) * 32;

    // cp.async load mapping: thread covers one 16B chunk of one row
    const int lrow = tid >> 1;
    const int lc   = tid & 1;
    const __half* Ah = g_xh + (size_t)(bm + lrow) * D_MODEL + lc * 8;
    const __half* Bh = g_wh + (size_t)(bn + lrow) * D_MODEL + lc * 8;
    const uint32_t dstA0 = smem_u32(&As2[0][lrow][lc * 4]);
    const uint32_t dstB0 = smem_u32(&Bs2[0][lrow][lc * 4]);

    // ldmatrix per-lane base addresses (stage 0)
    //   A mat layout: lanes 0-7 rows g k0 | 8-15 rows g+8 k0 | 16-23 rows g k8 | 24-31 rows g+8 k8
    const int arow = wm + (lane & 15);
    const int acol = (lane >> 4) * 4;
    uint32_t aBase[4];
    #pragma unroll
    for (int i = 0; i < 4; i++)
        aBase[i] = smem_u32(&As2[0][arow + i * 16][acol]);
    //   B pairs: lanes 0-7 rows n k0 | 8-15 rows n k8 | 16-23 rows n+8 k0 | 24-31 rows n+8 k8
    const int brow = wn + ((lane & 7) | ((lane & 16) >> 1));
    const int bcol = ((lane >> 3) & 1) * 4;
    uint32_t bBase[2];
    #pragma unroll
    for (int jp = 0; jp < 2; jp++)
        bBase[jp] = smem_u32(&Bs2[0][brow + jp * 16][bcol]);

    float acc[4][4][4];
    #pragma unroll
    for (int i = 0; i < 4; i++)
        #pragma unroll
        for (int j = 0; j < 4; j++)
            #pragma unroll
            for (int r = 0; r < 4; r++) acc[i][j][r] = 0.0f;

    const int NIT = D_MODEL / BK;   // 256

    // group c loads chunk c into stage c%3
    #define ISSUE_STAGE(c) do {                                                      \
        if ((c) < NIT) {                                                             \
            const uint32_t da = dstA0 + ((c) % NSTAGE) * STAGE_A_BYTES;              \
            const uint32_t db = dstB0 + ((c) % NSTAGE) * STAGE_B_BYTES;              \
            asm volatile("cp.async.cg.shared.global [%0], [%1], 16;"                 \
                         :: "r"(da), "l"(Ah + (c) * BK) : "memory");                 \
            asm volatile("cp.async.cg.shared.global [%0], [%1], 16;"                 \
                         :: "r"(db), "l"(Bh + (c) * BK) : "memory");                 \
        }                                                                            \
        asm volatile("cp.async.commit_group;" ::: "memory");                         \
    } while (0)

    ISSUE_STAGE(0);
    ISSUE_STAGE(1);

    #pragma unroll 1
    for (int it = 0; it < NIT; it++) {
        const int s = it % NSTAGE;
        asm volatile("cp.async.wait_group 1;" ::: "memory");   // chunk `it` resident
        __syncthreads();                                       // visible to all; prev compute done
        ISSUE_STAGE(it + 2);

        uint32_t af[4][4], bf[4][2];
        const uint32_t aoff = s * STAGE_A_BYTES;
        const uint32_t boff = s * STAGE_B_BYTES;
        #pragma unroll
        for (int i = 0; i < 4; i++)
            ldsm_x4(af[i][0], af[i][1], af[i][2], af[i][3], aBase[i] + aoff);
        #pragma unroll
        for (int jp = 0; jp < 2; jp++)
            ldsm_x4(bf[2 * jp][0], bf[2 * jp][1], bf[2 * jp + 1][0], bf[2 * jp + 1][1],
                    bBase[jp] + boff);

        #pragma unroll
        for (int i = 0; i < 4; i++)
            #pragma unroll
            for (int j = 0; j < 4; j++)
                mma_f16(acc[i][j], af[i][0], af[i][1], af[i][2], af[i][3],
                        bf[j][0], bf[j][1]);
    }
    #undef ISSUE_STAGE

    // epilogue
    #pragma unroll
    for (int i = 0; i < 4; i++) {
        const int r0 = bm + wm + i * 16 + g;
        #pragma unroll
        for (int j = 0; j < 4; j++) {
            const int c0 = bn + wn + j * 8 + 2 * t;
            const float bz0 = bias[c0], bz1 = bias[c0 + 1];
            float* p0 = C + (size_t)r0 * D_SAE + c0;
            float* p1 = C + (size_t)(r0 + 8) * D_SAE + c0;
            *(float2*)p0 = make_float2(acc[i][j][0] + bz0, acc[i][j][1] + bz1);
            *(float2*)p1 = make_float2(acc[i][j][2] + bz0, acc[i][j][3] + bz1);
        }
    }
}

// ================= top-k (radix select over SMEM-cached row + borderline recheck) =====
__device__ __forceinline__ unsigned fkey(float v) {
    unsigned u = __float_as_uint(v);
    return (u & 0x80000000u) ? ~u : (u | 0x80000000u);
}
__device__ __forceinline__ float key_to_float(unsigned k) {
    unsigned u = (k & 0x80000000u) ? (k & 0x7FFFFFFFu) : ~k;
    return __uint_as_float(u);
}
#define TK_MARGIN 4e-3f
#define MAX_BL 128

__global__ void topk_kernel(const float* __restrict__ pre,
                            float* __restrict__ sparse,
                            const float* __restrict__ x,
                            const float* __restrict__ W_enc,
                            const float* __restrict__ b_enc)
{
    extern __shared__ float srow_s[];          // 16384 floats = 64 KB row cache
    const int token = blockIdx.x;
    const float* row = pre + (size_t)token * D_SAE;
    float* srow = sparse + (size_t)token * D_SAE;
    const int tid = threadIdx.x;   // 256

    __shared__ unsigned hist[256];
    __shared__ unsigned s_prefix;
    __shared__ int s_remk, s_cnt, s_sure, s_nbl;
    __shared__ int s_bl[MAX_BL];
    __shared__ float s_bl_exact[MAX_BL];
    __shared__ unsigned char s_bl_take[MAX_BL];
    __shared__ float s_red[256];

    #pragma unroll
    for (int t4 = 0; t4 < 16; t4++) {
        const int i4 = tid + t4 * 256;
        ((float4*)srow_s)[i4] = ((const float4*)row)[i4];
    }
    __syncthreads();

    unsigned prefix = 0;
    int remk = K_SPARSE;
    for (int shift = 24; shift >= 0; shift -= 8) {
        hist[tid] = 0;
        __syncthreads();
        const unsigned hi_mask = (shift == 24) ? 0u : (0xFFFFFFFFu << (shift + 8));
        for (int i = tid; i < D_SAE; i += 256) {
            unsigned key = fkey(srow_s[i]);
            if ((key & hi_mask) == (prefix & hi_mask))
                atomicAdd(&hist[(key >> shift) & 0xFFu], 1u);
        }
        __syncthreads();
        if (tid == 0) {
            int r = remk, b = 255;
            for (; b > 0; b--) { int c = (int)hist[b]; if (c >= r) break; r -= c; }
            s_prefix = prefix | ((unsigned)b << shift);
            s_remk = r;
        }
        __syncthreads();
        prefix = s_prefix; remk = s_remk;
        __syncthreads();
    }

    const float tval = key_to_float(prefix);
    const float thi = tval + TK_MARGIN, tlo = tval - TK_MARGIN;

    if (tid == 0) { s_sure = 0; s_nbl = 0; s_cnt = 0; }
    __syncthreads();

    int local_sure = 0;
    for (int i = tid; i < D_SAE; i += 256) {
        float v = srow_s[i];
        if (v > thi) local_sure++;
        else if (v >= tlo) {
            int p = atomicAdd(&s_nbl, 1);
            if (p < MAX_BL) s_bl[p] = i;
        }
    }
    atomicAdd(&s_sure, local_sure);
    __syncthreads();

    const int nbl = (s_nbl < MAX_BL) ? s_nbl : MAX_BL;
    const int need = K_SPARSE - s_sure;

    if (nbl > need) {
        const float* xrow = x + (size_t)token * D_MODEL;
        for (int b = 0; b < nbl; b++) {
            const float* wrow = W_enc + (size_t)s_bl[b] * D_MODEL;
            float p = 0.0f;
            for (int j = tid; j < D_MODEL; j += 256)
                p = fmaf(xrow[j], wrow[j], p);
            s_red[tid] = p;
            __syncthreads();
            for (int st = 128; st > 0; st >>= 1) {
                if (tid < st) s_red[tid] += s_red[tid + st];
                __syncthreads();
            }
            if (tid == 0) s_bl_exact[b] = s_red[0] + b_enc[s_bl[b]];
            __syncthreads();
        }
        if (tid == 0) {
            for (int b = 0; b < nbl; b++) {
                int rank = 0;
                for (int b2 = 0; b2 < nbl; b2++) {
                    if (s_bl_exact[b2] > s_bl_exact[b] ||
                        (s_bl_exact[b2] == s_bl_exact[b] && b2 < b)) rank++;
                }
                s_bl_take[b] = (rank < need) ? 1 : 0;
            }
        }
    } else {
        if (tid == 0)
            for (int b = 0; b < nbl; b++) s_bl_take[b] = 1;
    }
    __syncthreads();

    float* vout = g_vals + (size_t)token * K_SPARSE;
    int*   iout = g_idxs + (size_t)token * K_SPARSE;

    for (int i = tid; i < D_SAE; i += 256) {
        float v = srow_s[i];
        bool take = (v > thi);
        if (!take && v >= tlo) {
            for (int b = 0; b < nbl; b++)
                if (s_bl[b] == i) { take = (s_bl_take[b] != 0); break; }
        }
        float outv = 0.0f;
        if (take) {
            outv = v;
            int slot = atomicAdd(&s_cnt, 1);
            if (slot < K_SPARSE) { vout[slot] = v; iout[slot] = i; }
        }
        srow[i] = outv;
    }
}

// ---- transpose W_dec (D_MODEL x D_SAE) -> g_WdecTh (D_SAE x D_MODEL), half ----
__global__ void transpose_kernel(const float* __restrict__ src)
{
    __shared__ float tile[32][33];
    const int f0 = blockIdx.x * 32;
    const int d0 = blockIdx.y * 32;
    const int tx = threadIdx.x, ty = threadIdx.y;   // (32, 8)
    #pragma unroll
    for (int i = 0; i < 32; i += 8)
        tile[ty + i][tx] = src[(size_t)(d0 + ty + i) * D_SAE + f0 + tx];
    __syncthreads();
    #pragma unroll
    for (int i = 0; i < 32; i += 8)
        g_WdecTh[(size_t)(f0 + ty + i) * D_MODEL + d0 + tx] =
            __float2half_rn(tile[tx][ty + i]);
}

// ---------------- sparse decoder: recon = sparse @ W_dec^T + b_dec (half weights) ------
__global__ __launch_bounds__(256)
void decoder_kernel(const float* __restrict__ b_dec,
                    float* __restrict__ recon)
{
    const int token = blockIdx.x;
    const int tid = threadIdx.x;

    __shared__ float s_v[K_SPARSE];
    __shared__ int   s_f[K_SPARSE];
    if (tid < K_SPARSE) {
        s_v[tid] = g_vals[(size_t)token * K_SPARSE + tid];
        s_f[tid] = g_idxs[(size_t)token * K_SPARSE + tid];
    }
    __syncthreads();

    float2 acc[8];
    #pragma unroll
    for (int i = 0; i < 8; i++)
        acc[i] = *(const float2*)(b_dec + 2 * (tid + i * 256));

    for (int j = 0; j < K_SPARSE; j++) {
        const float v = s_v[j];
        const __half2* w = (const __half2*)(g_WdecTh + (size_t)s_f[j] * D_MODEL);
        #pragma unroll
        for (int i = 0; i < 8; i++) {
            float2 f = __half22float2(w[tid + i * 256]);
            acc[i].x = fmaf(v, f.x, acc[i].x);
            acc[i].y = fmaf(v, f.y, acc[i].y);
        }
    }

    float* out = recon + (size_t)token * D_MODEL;
    #pragma unroll
    for (int i = 0; i < 8; i++)
        *(float2*)(out + 2 * (tid + i * 256)) = acc[i];
}

// ---------------- launch ----------------
extern "C" void kernel_launch(void* const* d_in, const int* in_sizes, int n_in,
                              void* d_out, int out_size)
{
    const float* x     = (const float*)d_in[0];
    const float* W_enc = (const float*)d_in[1];
    const float* b_enc = (const float*)d_in[2];
    const float* W_dec = (const float*)d_in[3];
    const float* b_dec = (const float*)d_in[4];

    float* out    = (float*)d_out;
    float* recon  = out;
    float* sparse = recon  + (size_t)N_TOKENS * D_MODEL;
    float* pre    = sparse + (size_t)N_TOKENS * D_SAE;

    cudaFuncSetAttribute(topk_kernel, cudaFuncAttributeMaxDynamicSharedMemorySize, 65536);

    // 0) convert x, W_enc to half
    f2h_all<<<(D_SAE * (D_MODEL / 4) + 255) / 256, 256>>>(x, W_enc);

    // 1) encoder GEMM on tensor cores (cp.async + ldmatrix + mma.sync fp16) -> pre_acts
    encoder_mma<<<TILES_M * TILES_N, 256>>>(b_enc, pre);

    // 2) transpose + half-convert W_dec for the sparse decoder
    transpose_kernel<<<dim3(D_SAE / 32, D_MODEL / 32), dim3(32, 8)>>>(W_dec);

    // 3) per-token top-64 with SMEM row cache + borderline exact recheck
    topk_kernel<<<N_TOKENS, 256, 65536>>>(pre, sparse, x, W_enc, b_enc);

    // 4) sparse decoder (half weights, fp32 accumulate) -> reconstruction
    decoder_kernel<<<N_TOKENS, 256>>>(b_dec, recon);
}